// round 2
// baseline (speedup 1.0000x reference)
#include <cuda_runtime.h>
#include <cstdint>

// PatchTransformer: paste 8 translated, bilinearly-resampled 256x256x3 patches
// onto a 3x1024x1024 image. Exact-fp replication of the reference's
// grid_sample arithmetic (rn intrinsics block FMA contraction) because the
// reference gates on mask == 1.0 and adv == 0.0 equality.
//
// R2: per-block patch culling (x ~ w - 512*lx, conservative +-2px margin),
// float4-vectorized clean/out path, y-chain hoisted per thread (4 pixels
// share h).

#define S 1024
#define PS 256
#define NPATCH 8

__global__ __launch_bounds__(256)
void patch_transformer_kernel(const float* __restrict__ patches,   // [8,3,256,256]
                              const float* __restrict__ locs,      // [8,2]
                              const float* __restrict__ clean,     // [3,1024,1024]
                              float* __restrict__ out)             // [3,1024,1024]
{
    __shared__ float sloc[2 * NPATCH];
    __shared__ unsigned smask;

    const int tid = threadIdx.y * 32 + threadIdx.x;
    if (tid < 2 * NPATCH) sloc[tid] = locs[tid];

    const int bw0 = blockIdx.x * 128;   // block covers w in [bw0, bw0+127]
    const int bh0 = blockIdx.y * 8;     // block covers h in [bh0, bh0+7]

    if (tid == 0) {
        // Conservative footprint cull. Exact x satisfies |x - (w - 512*lx)| << 1,
        // pixel is active iff floor(x) in [-1,256] i.e. x in [-1,257).
        // Use +-2 margin -> patch active in w iff w in [512lx-3, 512lx+259].
        unsigned m = 0;
        #pragma unroll
        for (int n = 0; n < NPATCH; ++n) {
            const float px = 512.0f * locs[2 * n + 0];
            const float py = 512.0f * locs[2 * n + 1];
            const bool ax = ((float)bw0        <= px + 259.0f) &&
                            ((float)(bw0+127)  >= px - 3.0f);
            const bool ay = ((float)bh0        <= py + 259.0f) &&
                            ((float)(bh0+7)    >= py - 3.0f);
            if (ax && ay) m |= (1u << n);
        }
        smask = m;
    }
    __syncthreads();

    const int w0 = bw0 + threadIdx.x * 4;
    const int h  = bh0 + threadIdx.y;
    const int pix = h * S + w0;

    float4 v0 = *(const float4*)(clean + pix);
    float4 v1 = *(const float4*)(clean + pix + S * S);
    float4 v2 = *(const float4*)(clean + pix + 2 * S * S);
    float v[3][4] = {{v0.x, v0.y, v0.z, v0.w},
                     {v1.x, v1.y, v1.z, v1.w},
                     {v2.x, v2.y, v2.z, v2.w}};

    // Normalized grid coords, exact reference chain (all exact fp32 here).
    float gx[4];
    #pragma unroll
    for (int k = 0; k < 4; ++k)
        gx[k] = __fadd_rn(__fmul_rn(__fmul_rn(__fadd_rn((float)(w0 + k), 0.5f), 2.0f),
                                    (1.0f / 1024.0f)), -1.0f);
    const float gy = __fadd_rn(__fmul_rn(__fmul_rn(__fadd_rn((float)h, 0.5f), 2.0f),
                                         (1.0f / 1024.0f)), -1.0f);

    unsigned mask = smask;
    while (mask) {
        const int n = __ffs(mask) - 1;
        mask &= mask - 1;

        const float lx = sloc[2 * n + 0];
        const float ly = sloc[2 * n + 1];

        // y chain shared by all 4 pixels of this thread.
        const float gry = __fadd_rn(gy, -ly);
        const float y = __fmul_rn(__fadd_rn(__fmul_rn(__fadd_rn(gry, 1.0f), 1024.0f), -1.0f), 0.5f);
        const float y0f = floorf(y);
        const int iy0 = (int)y0f;
        if ((unsigned)(iy0 + 1) > 256u) continue;   // no tap hits patch rows

        const float wy1 = __fadd_rn(y, -y0f);
        const float wy0 = __fadd_rn(1.0f, -wy1);
        const bool vy0 = (iy0 >= 0);            // also cy0
        const bool cy1 = (iy0 <= PS - 2);

        const float* P = patches + (size_t)n * 3 * PS * PS;
        const int rowoff = iy0 * PS;

        #pragma unroll
        for (int k = 0; k < 4; ++k) {
            const float grx = __fadd_rn(gx[k], -lx);
            const float x = __fmul_rn(__fadd_rn(__fmul_rn(__fadd_rn(grx, 1.0f), 1024.0f), -1.0f), 0.5f);
            const float x0f = floorf(x);
            const int ix0 = (int)x0f;
            if ((unsigned)(ix0 + 1) > 256u) continue;

            const float wx1 = __fadd_rn(x, -x0f);
            const float wx0 = __fadd_rn(1.0f, -wx1);

            const float w00 = __fmul_rn(wy0, wx0);
            const float w01 = __fmul_rn(wy0, wx1);
            const float w10 = __fmul_rn(wy1, wx0);
            const float w11 = __fmul_rn(wy1, wx1);

            const bool vx0 = (ix0 >= 0);        // also cx0
            // mask_w = left-associated sum of valid*weight, exactly as reference.
            const float m = __fadd_rn(__fadd_rn(__fadd_rn(
                                (vy0 && vx0) ? w00 : 0.0f,
                                vy0 ? w01 : 0.0f),
                                vx0 ? w10 : 0.0f),
                                w11);
            if (m != 1.0f) continue;

            const bool cx1 = (ix0 <= PS - 2);
            const bool t00v = vy0 && vx0;
            const bool t01v = vy0 && cx1;
            const bool t10v = cy1 && vx0;
            const bool t11v = cy1 && cx1;
            if (!(t00v | t01v | t10v | t11v)) continue;

            const int o00 = rowoff + ix0;
            #pragma unroll
            for (int c = 0; c < 3; ++c) {
                const float* B = P + c * PS * PS;
                const float t00 = t00v ? __fmul_rn(__ldg(B + o00),          w00) : 0.0f;
                const float t01 = t01v ? __fmul_rn(__ldg(B + o00 + 1),      w01) : 0.0f;
                const float t10 = t10v ? __fmul_rn(__ldg(B + o00 + PS),     w10) : 0.0f;
                const float t11 = t11v ? __fmul_rn(__ldg(B + o00 + PS + 1), w11) : 0.0f;
                const float p = __fadd_rn(__fadd_rn(__fadd_rn(t00, t01), t10), t11);
                if (p != 0.0f) v[c][k] = p;
            }
        }
    }

    *(float4*)(out + pix)             = make_float4(v[0][0], v[0][1], v[0][2], v[0][3]);
    *(float4*)(out + pix + S * S)     = make_float4(v[1][0], v[1][1], v[1][2], v[1][3]);
    *(float4*)(out + pix + 2 * S * S) = make_float4(v[2][0], v[2][1], v[2][2], v[2][3]);
}

extern "C" void kernel_launch(void* const* d_in, const int* in_sizes, int n_in,
                              void* d_out, int out_size) {
    const float* patches = (const float*)d_in[0];   // (8,3,256,256)
    const float* locs    = (const float*)d_in[1];   // (8,2)
    const float* clean   = (const float*)d_in[2];   // (3,1024,1024)
    float* out = (float*)d_out;                     // (1,3,1024,1024)

    dim3 block(32, 8);                  // each thread: 4 pixels in w
    dim3 grid(S / 128, S / 8);          // 8 x 128 = 1024 blocks
    patch_transformer_kernel<<<grid, block>>>(patches, locs, clean, out);
}

// round 3
// speedup vs baseline: 1.5141x; 1.5141x over previous
#include <cuda_runtime.h>
#include <cstdint>

// PatchTransformer: paste 8 translated, bilinearly-resampled 256x256x3 patches
// onto a 3x1024x1024 image. Exact-fp replication of the reference's
// grid_sample arithmetic (rn intrinsics block FMA contraction) because the
// reference gates on mask == 1.0 and adv == 0.0 equality.
//
// R3: block-level patch culling + 2px/thread float2 path + occupancy cap
// (launch_bounds(256,8) -> regs<=32, 8 CTA/SM) + 2048-block grid for balance.

#define S 1024
#define PS 256
#define NPATCH 8

__global__ __launch_bounds__(256, 8)
void patch_transformer_kernel(const float* __restrict__ patches,   // [8,3,256,256]
                              const float* __restrict__ locs,      // [8,2]
                              const float* __restrict__ clean,     // [3,1024,1024]
                              float* __restrict__ out)             // [3,1024,1024]
{
    __shared__ float sloc[2 * NPATCH];
    __shared__ unsigned smask;

    const int tid = threadIdx.y * 32 + threadIdx.x;
    if (tid < 2 * NPATCH) sloc[tid] = locs[tid];

    const int bw0 = blockIdx.x * 64;    // block covers w in [bw0, bw0+63]
    const int bh0 = blockIdx.y * 8;     // block covers h in [bh0, bh0+7]

    if (tid == 0) {
        // Conservative footprint cull. Exact x satisfies |x - (w - 512*lx)| << 1;
        // pixel can touch the patch iff floor(x) in [-1,256], i.e. x in [-1,257).
        // +-3px margin -> active iff w in [512lx-3, 512lx+259].
        unsigned m = 0;
        #pragma unroll
        for (int n = 0; n < NPATCH; ++n) {
            const float px = 512.0f * locs[2 * n + 0];
            const float py = 512.0f * locs[2 * n + 1];
            const bool ax = ((float)bw0       <= px + 259.0f) &&
                            ((float)(bw0+63)  >= px - 3.0f);
            const bool ay = ((float)bh0       <= py + 259.0f) &&
                            ((float)(bh0+7)   >= py - 3.0f);
            if (ax && ay) m |= (1u << n);
        }
        smask = m;
    }
    __syncthreads();

    const int w0 = bw0 + threadIdx.x * 2;
    const int h  = bh0 + threadIdx.y;
    const int pix = h * S + w0;

    float2 v0 = *(const float2*)(clean + pix);
    float2 v1 = *(const float2*)(clean + pix + S * S);
    float2 v2 = *(const float2*)(clean + pix + 2 * S * S);
    float v[3][2] = {{v0.x, v0.y}, {v1.x, v1.y}, {v2.x, v2.y}};

    unsigned mask = smask;
    if (mask) {
        // Normalized grid coords, exact reference chain (all steps exact fp32).
        float gx[2];
        #pragma unroll
        for (int k = 0; k < 2; ++k)
            gx[k] = __fadd_rn(__fmul_rn(__fmul_rn(__fadd_rn((float)(w0 + k), 0.5f), 2.0f),
                                        (1.0f / 1024.0f)), -1.0f);
        const float gy = __fadd_rn(__fmul_rn(__fmul_rn(__fadd_rn((float)h, 0.5f), 2.0f),
                                             (1.0f / 1024.0f)), -1.0f);

        do {
            const int n = __ffs(mask) - 1;
            mask &= mask - 1;

            const float lx = sloc[2 * n + 0];
            const float ly = sloc[2 * n + 1];

            // y chain shared by both pixels of this thread.
            const float gry = __fadd_rn(gy, -ly);
            const float y = __fmul_rn(__fadd_rn(__fmul_rn(__fadd_rn(gry, 1.0f), 1024.0f), -1.0f), 0.5f);
            const float y0f = floorf(y);
            const int iy0 = (int)y0f;
            if ((unsigned)(iy0 + 1) > 256u) continue;   // no tap hits patch rows

            const float wy1 = __fadd_rn(y, -y0f);
            const float wy0 = __fadd_rn(1.0f, -wy1);
            const bool vy0 = (iy0 >= 0);            // also cy0
            const bool cy1 = (iy0 <= PS - 2);

            const float* P = patches + (size_t)n * 3 * PS * PS;
            const int rowoff = iy0 * PS;

            #pragma unroll
            for (int k = 0; k < 2; ++k) {
                const float grx = __fadd_rn(gx[k], -lx);
                const float x = __fmul_rn(__fadd_rn(__fmul_rn(__fadd_rn(grx, 1.0f), 1024.0f), -1.0f), 0.5f);
                const float x0f = floorf(x);
                const int ix0 = (int)x0f;
                if ((unsigned)(ix0 + 1) > 256u) continue;

                const float wx1 = __fadd_rn(x, -x0f);
                const float wx0 = __fadd_rn(1.0f, -wx1);

                const float w00 = __fmul_rn(wy0, wx0);
                const float w01 = __fmul_rn(wy0, wx1);
                const float w10 = __fmul_rn(wy1, wx0);
                const float w11 = __fmul_rn(wy1, wx1);

                const bool vx0 = (ix0 >= 0);        // also cx0
                // mask_w = left-associated sum of valid*weight, exactly as reference.
                const float m = __fadd_rn(__fadd_rn(__fadd_rn(
                                    (vy0 && vx0) ? w00 : 0.0f,
                                    vy0 ? w01 : 0.0f),
                                    vx0 ? w10 : 0.0f),
                                    w11);
                if (m != 1.0f) continue;

                const bool cx1 = (ix0 <= PS - 2);
                const bool t00v = vy0 && vx0;
                const bool t01v = vy0 && cx1;
                const bool t10v = cy1 && vx0;
                const bool t11v = cy1 && cx1;
                if (!(t00v | t01v | t10v | t11v)) continue;

                const int o00 = rowoff + ix0;
                #pragma unroll
                for (int c = 0; c < 3; ++c) {
                    const float* B = P + c * PS * PS;
                    const float t00 = t00v ? __fmul_rn(__ldg(B + o00),          w00) : 0.0f;
                    const float t01 = t01v ? __fmul_rn(__ldg(B + o00 + 1),      w01) : 0.0f;
                    const float t10 = t10v ? __fmul_rn(__ldg(B + o00 + PS),     w10) : 0.0f;
                    const float t11 = t11v ? __fmul_rn(__ldg(B + o00 + PS + 1), w11) : 0.0f;
                    const float p = __fadd_rn(__fadd_rn(__fadd_rn(t00, t01), t10), t11);
                    if (p != 0.0f) v[c][k] = p;
                }
            }
        } while (mask);
    }

    *(float2*)(out + pix)             = make_float2(v[0][0], v[0][1]);
    *(float2*)(out + pix + S * S)     = make_float2(v[1][0], v[1][1]);
    *(float2*)(out + pix + 2 * S * S) = make_float2(v[2][0], v[2][1]);
}

extern "C" void kernel_launch(void* const* d_in, const int* in_sizes, int n_in,
                              void* d_out, int out_size) {
    const float* patches = (const float*)d_in[0];   // (8,3,256,256)
    const float* locs    = (const float*)d_in[1];   // (8,2)
    const float* clean   = (const float*)d_in[2];   // (3,1024,1024)
    float* out = (float*)d_out;                     // (1,3,1024,1024)

    dim3 block(32, 8);                  // each thread: 2 pixels in w (float2)
    dim3 grid(S / 64, S / 8);           // 16 x 128 = 2048 blocks
    patch_transformer_kernel<<<grid, block>>>(patches, locs, clean, out);
}